// round 4
// baseline (speedup 1.0000x reference)
#include <cuda_runtime.h>
#include <cuda_bf16.h>
#include <cuda_fp8.h>
#include <math.h>
#include <stdint.h>

// Problem constants
#define N_SEQ   4096
#define N_DOCS  512
#define EMBD    300
#define HID     256
#define GATES   1024
#define T_COL   64
#define T_ROW   16

// Tiling (FP8: k-tiles of 32)
#define MCH     32          // sequences per block
#define NKT     18          // 18*32 = 576 (556 real + pad)
#define ASB     592         // A row stride bytes (148 words)
#define AKW     148
#define NTHREADS 512        // 16 warps, 8 n-tiles each

#define SCL     16.0f
#define ISCL    0.00390625f // 1/256

// smem offsets (bytes)
#define SM_AS    0
#define SM_CS    (MCH*ASB)                  // 18944
#define SM_HS    (SM_CS + MCH*257*4)        // 51840
#define SM_BIAS  (SM_HS + MCH*257*4)        // 84736
#define SM_LENS  (SM_BIAS + GATES*4)        // 88832
#define SM_TOKS  (SM_LENS + 128)            // 88960
#define SMEM_BYTES (SM_TOKS + 128)          // 89088

// ---------------- device scratch ----------------
__device__ uint2  g_Bpack[2][NKT][128][32];     // 1.18 MB fp8 fragments
__device__ float  g_bias[2][GATES];
__device__ float  g_acc[3][N_DOCS][HID];

// ---------------- helpers ----------------
__device__ __forceinline__ float ftanh(float x) {
    float y; asm("tanh.approx.f32 %0, %1;" : "=f"(y) : "f"(x)); return y;
}
__device__ __forceinline__ float fsigm(float x) {
    return 0.5f * ftanh(0.5f * x) + 0.5f;
}
__device__ __forceinline__ uint32_t pack4_e4m3(float v0, float v1, float v2, float v3) {
    uint16_t lo, hi;
    asm("cvt.rn.satfinite.e4m3x2.f32 %0, %1, %2;" : "=h"(lo) : "f"(v1), "f"(v0));
    asm("cvt.rn.satfinite.e4m3x2.f32 %0, %1, %2;" : "=h"(hi) : "f"(v3), "f"(v2));
    return (uint32_t)lo | ((uint32_t)hi << 16);
}
__device__ __forceinline__ uint8_t f_to_e4m3(float v) {
    uint16_t r;
    asm("cvt.rn.satfinite.e4m3x2.f32 %0, %1, %2;" : "=h"(r) : "f"(0.f), "f"(v));
    return (uint8_t)r;
}
__device__ __forceinline__ void mma16832(float* c, const uint32_t* a, uint2 b) {
    asm volatile(
        "mma.sync.aligned.m16n8k32.row.col.f32.e4m3.e4m3.f32 "
        "{%0,%1,%2,%3},{%4,%5,%6,%7},{%8,%9},{%0,%1,%2,%3};"
        : "+f"(c[0]), "+f"(c[1]), "+f"(c[2]), "+f"(c[3])
        : "r"(a[0]), "r"(a[1]), "r"(a[2]), "r"(a[3]), "r"(b.x), "r"(b.y));
}

// ---------------- prep ----------------
__global__ void prep_kernel(const float* cWih, const float* cWhh,
                            const float* cbih, const float* cbhh,
                            const float* rWih, const float* rWhh,
                            const float* rbih, const float* rbhh,
                            float* out) {
    int idx = blockIdx.x * blockDim.x + threadIdx.x;
    if (idx == 0) *out = 0.f;
    if (idx < 3 * N_DOCS * HID) (&g_acc[0][0][0])[idx] = 0.f;

    if (idx < 2 * GATES) {
        int bm = idx >> 10, jb = idx & 1023;
        int jbo = (jb & 3) * 256 + (jb >> 2);
        const float* bih = bm ? rbih : cbih;
        const float* bhh = bm ? rbhh : cbhh;
        g_bias[bm][jb] = bih[jbo] + bhh[jbo];
    }

    if (idx < 2 * NKT * 128 * 32) {
        int lane = idx & 31;
        int ntg  = (idx >> 5) & 127;
        int q    = idx >> 12;
        int kt   = q % NKT;
        int mat  = q / NKT;
        const float* Wih = mat ? rWih : cWih;
        const float* Whh = mat ? rWhh : cWhh;

        int tg = lane & 3, gg = lane >> 2;
        int jp = ntg * 8 + gg;
        int jo = (jp & 3) * 256 + (jp >> 2);
        int k0 = kt * 32 + 4 * tg;

        float v[8];
        #pragma unroll
        for (int i = 0; i < 8; i++) {
            int k = k0 + (i >> 2) * 16 + (i & 3);
            float f = 0.f;
            if (k < EMBD)            f = Wih[jo * EMBD + k];
            else if (k < EMBD + HID) f = Whh[jo * HID + (k - EMBD)];
            v[i] = SCL * f;
        }
        uint2 w2;
        w2.x = pack4_e4m3(v[0], v[1], v[2], v[3]);
        w2.y = pack4_e4m3(v[4], v[5], v[6], v[7]);
        g_Bpack[mat][kt][ntg][lane] = w2;
    }
}

__global__ void dummy_kernel() {}

// ---------------- main fused LSTM kernel ----------------
__global__ void __launch_bounds__(NTHREADS, 1)
lstm_kernel(const int* colT, const int* rowT, const int* negT,
            const int* clen, const int* rlen, const int* nlen,
            const int* cref, const int* rref, const int* nref,
            const float* emb) {
    extern __shared__ char smem[];
    uint8_t*  As   = (uint8_t*)(smem + SM_AS);     // [MCH][ASB] e4m3
    float*    Cs   = (float*)(smem + SM_CS);       // [MCH][257]
    float*    Hs   = (float*)(smem + SM_HS);       // [MCH][257]
    float*    bias = (float*)(smem + SM_BIAS);     // [1024]
    int*      lensS= (int*)(smem + SM_LENS);
    int*      toksS= (int*)(smem + SM_TOKS);

    // --- LPT-ish job order: col chunks first (longest chains), then row/neg interleaved ---
    int bid = blockIdx.x;
    int task, chunk;
    if (bid < 128) { task = 0; chunk = bid; }
    else           { int j = bid - 128; task = 1 + (j & 1); chunk = j >> 1; }
    int n0 = chunk * MCH;

    const int* toks; const int* lens; const int* refs; int T; int mat;
    if (task == 0)      { toks = colT; lens = clen; refs = cref; T = T_COL; mat = 0; }
    else if (task == 1) { toks = rowT; lens = rlen; refs = rref; T = T_ROW; mat = 1; }
    else                { toks = negT; lens = nlen; refs = nref; T = T_ROW; mat = 1; }

    int tid = threadIdx.x;
    int w = tid >> 5, lane = tid & 31;
    int tg = lane & 3, gg = lane >> 2;

    // --- init smem ---
    for (int i = tid; i < GATES; i += NTHREADS) bias[i] = g_bias[mat][i];
    for (int i = tid; i < 2 * MCH * 257; i += NTHREADS) Cs[i] = 0.f;   // Cs + Hs adjacent
    {   // zero h-region + pad: words [75,148) of each A row
        uint32_t* Aw0 = (uint32_t*)As;
        for (int i = tid; i < MCH * 73; i += NTHREADS) {
            int m = i / 73, kk = 75 + i % 73;
            Aw0[m * AKW + kk] = 0u;
        }
    }
    if (tid < MCH) lensS[tid] = lens[n0 + tid];
    __syncthreads();

    int maxlen = 0;
    #pragma unroll
    for (int i = 0; i < MCH; i++) maxlen = max(maxlen, lensS[i]);

    const uint32_t* Aw = (const uint32_t*)As;
    // warp w owns n-tiles [w*8, w*8+8)
    const uint2* Bp = &g_Bpack[mat][0][0][0] + w * 8 * 32 + lane;
    const int a_base = gg * AKW + tg;

    const float4* emb4 = (const float4*)emb;

    for (int t = 0; t < maxlen; t++) {
        if (tid < MCH) toksS[tid] = toks[(n0 + tid) * T + t];
        __syncthreads();

        // gather x -> e4m3 (scaled): 16 threads per sequence row
        {
            int m = tid >> 4, ts = tid & 15;
            const float4* erow = emb4 + (size_t)toksS[m] * (EMBD / 4);
            uint32_t* arow = (uint32_t*)(As + m * ASB);
            for (int kk = ts; kk < EMBD / 4; kk += 16) {
                float4 v = __ldg(&erow[kk]);
                arow[kk] = pack4_e4m3(SCL * v.x, SCL * v.y, SCL * v.z, SCL * v.w);
            }
        }
        __syncthreads();

        // --- GEMM: [32,576] @ [576,1024] fp8, 16 warps x 8 ntiles ---
        float acc[2][8][4];
        #pragma unroll
        for (int mt = 0; mt < 2; mt++)
            #pragma unroll
            for (int nt = 0; nt < 8; nt++)
                #pragma unroll
                for (int i = 0; i < 4; i++) acc[mt][nt][i] = 0.f;

        #pragma unroll 3
        for (int kt = 0; kt < NKT; kt++) {
            uint32_t a[2][4];
            int ab = a_base + kt * 8;
            #pragma unroll
            for (int mt = 0; mt < 2; mt++) {
                int o = ab + mt * 16 * AKW;
                a[mt][0] = Aw[o];
                a[mt][1] = Aw[o + 8 * AKW];
                a[mt][2] = Aw[o + 4];
                a[mt][3] = Aw[o + 8 * AKW + 4];
            }
            const uint2* bk = Bp + (size_t)kt * 128 * 32;
            #pragma unroll
            for (int nt = 0; nt < 8; nt++) {
                uint2 b = __ldg(bk + nt * 32);
                mma16832(acc[0][nt], a[0], b);
                mma16832(acc[1][nt], a[1], b);
            }
        }
        __syncthreads();

        // --- epilogue ---
        bool ev = !(tg & 1);
        #pragma unroll
        for (int mt = 0; mt < 2; mt++) {
            #pragma unroll
            for (int nt = 0; nt < 8; nt++) {
                int jc = (w << 6) + (nt << 3) + (tg << 1);   // permuted col
                float b0 = bias[jc], b1 = bias[jc + 1];
                float x0 = acc[mt][nt][0] * ISCL + b0;
                float x1 = acc[mt][nt][1] * ISCL + b1;
                float x2 = acc[mt][nt][2] * ISCL + b0;
                float x3 = acc[mt][nt][3] * ISCL + b1;
                float y0 = __shfl_xor_sync(0xffffffffu, x0, 1);
                float y1 = __shfl_xor_sync(0xffffffffu, x1, 1);
                float y2 = __shfl_xor_sync(0xffffffffu, x2, 1);
                float y3 = __shfl_xor_sync(0xffffffffu, x3, 1);
                float pi = ev ? x0 : y2;
                float pf = ev ? x1 : y3;
                float pg = ev ? y0 : x2;
                float po = ev ? y1 : x3;
                int mrow = (mt << 4) + gg + (ev ? 0 : 8);
                int u = (w << 4) + (nt << 1) + (tg >> 1);    // hidden unit
                if (t < lensS[mrow]) {
                    float i_ = fsigm(pi), f_ = fsigm(pf), o_ = fsigm(po), g_ = ftanh(pg);
                    float cn = f_ * Cs[mrow * 257 + u] + i_ * g_;
                    Cs[mrow * 257 + u] = cn;
                    float hn = o_ * ftanh(cn);
                    Hs[mrow * 257 + u] = hn;
                    As[mrow * ASB + EMBD + u] = f_to_e4m3(SCL * hn);
                }
            }
        }
    }

    // --- scatter final h into doc accumulators ---
    __syncthreads();
    if (tid < MCH) toksS[tid] = refs[n0 + tid];
    __syncthreads();
    float* accb = &g_acc[task][0][0];
    for (int idx = tid; idx < MCH * HID; idx += NTHREADS) {
        int m = idx >> 8, u = idx & 255;
        atomicAdd(&accb[toksS[m] * HID + u], Hs[m * 257 + u]);
    }
}

// ---------------- loss ----------------
__global__ void loss_kernel(float* out) {
    int d = blockIdx.x;
    float cv = g_acc[0][d][threadIdx.x], rv = g_acc[1][d][threadIdx.x], nv = g_acc[2][d][threadIdx.x];
    float p = cv * rv, q = cv * nv;
    #pragma unroll
    for (int o = 16; o; o >>= 1) {
        p += __shfl_xor_sync(0xffffffffu, p, o);
        q += __shfl_xor_sync(0xffffffffu, q, o);
    }
    __shared__ float sp[8], sq[8];
    int w = threadIdx.x >> 5, l = threadIdx.x & 31;
    if (l == 0) { sp[w] = p; sq[w] = q; }
    __syncthreads();
    if (threadIdx.x == 0) {
        float P = 0.f, Q = 0.f;
        #pragma unroll
        for (int i = 0; i < 8; i++) { P += sp[i]; Q += sq[i]; }
        float x = P - Q;
        float lz = fmaxf(-x, 0.f) + log1pf(expf(-fabsf(x)));
        if (d == 0) lz += (float)((N_SEQ - N_DOCS) * 0.6931471805599453);
        atomicAdd(out, lz);
    }
}

// ---------------- launch ----------------
extern "C" void kernel_launch(void* const* d_in, const int* in_sizes, int n_in,
                              void* d_out, int out_size) {
    const int*   col   = (const int*)d_in[0];
    const int*   row   = (const int*)d_in[1];
    const int*   rng   = (const int*)d_in[2];
    const int*   clen  = (const int*)d_in[3];
    const int*   rlen  = (const int*)d_in[4];
    const int*   nlen  = (const int*)d_in[5];
    const int*   cref  = (const int*)d_in[6];
    const int*   rref  = (const int*)d_in[7];
    const int*   nref  = (const int*)d_in[8];
    const float* emb   = (const float*)d_in[9];
    const float* cWih  = (const float*)d_in[10];
    const float* cWhh  = (const float*)d_in[11];
    const float* cbih  = (const float*)d_in[12];
    const float* cbhh  = (const float*)d_in[13];
    const float* rWih  = (const float*)d_in[14];
    const float* rWhh  = (const float*)d_in[15];
    const float* rbih  = (const float*)d_in[16];
    const float* rbhh  = (const float*)d_in[17];
    float* out = (float*)d_out;

    cudaFuncSetAttribute(lstm_kernel, cudaFuncAttributeMaxDynamicSharedMemorySize, SMEM_BYTES);

    prep_kernel<<<1536, 256>>>(cWih, cWhh, cbih, cbhh, rWih, rWhh, rbih, rbhh, out);
    dummy_kernel<<<1, 32>>>();
    dummy_kernel<<<1, 32>>>();
    lstm_kernel<<<384, NTHREADS, SMEM_BYTES>>>(col, row, rng, clen, rlen, nlen,
                                               cref, rref, nref, emb);
    loss_kernel<<<N_DOCS, 256>>>(out);
}

// round 5
// speedup vs baseline: 1.2313x; 1.2313x over previous
#include <cuda_runtime.h>
#include <cuda_bf16.h>
#include <cuda_fp8.h>
#include <math.h>
#include <stdint.h>

// Problem constants
#define VOCAB   50000
#define N_SEQ   4096
#define N_DOCS  512
#define EMBD    300
#define HID     256
#define GATES   1024
#define T_COL   64
#define T_ROW   16

#define MCH     32          // sequences per block
#define NTHREADS 512        // 16 warps, 8 n-tiles each

// recurrence A (h, fp8): k=256 -> 8 kt, row stride 272 B (68 words, 68%32=4)
#define NKT_H   8
#define AKW     68
#define ASB     272
// xproj A (emb, fp8): k=300 pad 320 -> 10 kt, row stride 336 B (84 words, 84%32=20)
#define NKT_X   10
#define XKW     84
#define XSB     336

#define SCL     16.0f
#define ISCL    0.00390625f // 1/256

// lstm smem offsets (bytes)
#define SM_AS    0                          // 32*272   = 8704
#define SM_CS    8704                       // 32*257*4 = 32896
#define SM_HS    41600                      // 32896
#define SM_XS    74496                      // 32*2064  = 66048
#define SM_LENS  140544                     // 128
#define SM_TOKS  140672                     // 128
#define SMEM_BYTES 140800
#define XS_W     516                        // xs row stride in words (516%32=4)

// ---------------- device scratch ----------------
__device__ uint2  g_Whh[2][NKT_H][128][32];    // 512 KB fp8 fragments
__device__ uint2  g_Wih[2][NKT_X][128][32];    // 640 KB fp8 fragments
__device__ float  g_bias[2][GATES];
__device__ __nv_bfloat16 g_xproj[2][VOCAB][GATES];  // 204.8 MB (xproj + bias, permuted cols)
__device__ float  g_acc[3][N_DOCS][HID];

// ---------------- helpers ----------------
__device__ __forceinline__ float ftanh(float x) {
    float y; asm("tanh.approx.f32 %0, %1;" : "=f"(y) : "f"(x)); return y;
}
__device__ __forceinline__ float fsigm(float x) {
    return 0.5f * ftanh(0.5f * x) + 0.5f;
}
__device__ __forceinline__ uint32_t pack4_e4m3(float v0, float v1, float v2, float v3) {
    uint16_t lo, hi;
    asm("cvt.rn.satfinite.e4m3x2.f32 %0, %1, %2;" : "=h"(lo) : "f"(v1), "f"(v0));
    asm("cvt.rn.satfinite.e4m3x2.f32 %0, %1, %2;" : "=h"(hi) : "f"(v3), "f"(v2));
    return (uint32_t)lo | ((uint32_t)hi << 16);
}
__device__ __forceinline__ uint8_t f_to_e4m3(float v) {
    uint16_t r;
    asm("cvt.rn.satfinite.e4m3x2.f32 %0, %1, %2;" : "=h"(r) : "f"(0.f), "f"(v));
    return (uint8_t)r;
}
__device__ __forceinline__ uint32_t pack_bf16x2(float lo, float hi) {
    uint32_t r;
    asm("cvt.rn.bf16x2.f32 %0, %1, %2;" : "=r"(r) : "f"(hi), "f"(lo));
    return r;
}
__device__ __forceinline__ void mma16832(float* c, const uint32_t* a, uint2 b) {
    asm volatile(
        "mma.sync.aligned.m16n8k32.row.col.f32.e4m3.e4m3.f32 "
        "{%0,%1,%2,%3},{%4,%5,%6,%7},{%8,%9},{%0,%1,%2,%3};"
        : "+f"(c[0]), "+f"(c[1]), "+f"(c[2]), "+f"(c[3])
        : "r"(a[0]), "r"(a[1]), "r"(a[2]), "r"(a[3]), "r"(b.x), "r"(b.y));
}
__device__ __forceinline__ void cp_async16(uint32_t dst, const void* src) {
    asm volatile("cp.async.cg.shared.global [%0], [%1], 16;" :: "r"(dst), "l"(src));
}

// ---------------- prep: pack weights + bias, zero accumulators ----------------
__global__ void prep_kernel(const float* cWih, const float* cWhh,
                            const float* cbih, const float* cbhh,
                            const float* rWih, const float* rWhh,
                            const float* rbih, const float* rbhh,
                            float* out) {
    int idx = blockIdx.x * blockDim.x + threadIdx.x;   // 393216 threads
    if (idx == 0) *out = 0.f;
    if (idx < 3 * N_DOCS * HID) (&g_acc[0][0][0])[idx] = 0.f;

    if (idx < 2 * GATES) {
        int bm = idx >> 10, jb = idx & 1023;
        int jbo = (jb & 3) * 256 + (jb >> 2);
        const float* bih = bm ? rbih : cbih;
        const float* bhh = bm ? rbhh : cbhh;
        g_bias[bm][jb] = bih[jbo] + bhh[jbo];
    }

    int lane = idx & 31;
    int ntg  = (idx >> 5) & 127;
    int q    = idx >> 12;
    int tg = lane & 3, gg = lane >> 2;
    int jp = ntg * 8 + gg;
    int jo = (jp & 3) * 256 + (jp >> 2);

    if (idx < 2 * NKT_X * 128 * 32) {           // Wih pack (k = 0..299 pad 320)
        int kt  = q % NKT_X;
        int mat = q / NKT_X;
        const float* Wih = mat ? rWih : cWih;
        int k0 = kt * 32 + 4 * tg;
        float v[8];
        #pragma unroll
        for (int i = 0; i < 8; i++) {
            int k = k0 + (i >> 2) * 16 + (i & 3);
            v[i] = (k < EMBD) ? SCL * Wih[jo * EMBD + k] : 0.f;
        }
        uint2 w2;
        w2.x = pack4_e4m3(v[0], v[1], v[2], v[3]);
        w2.y = pack4_e4m3(v[4], v[5], v[6], v[7]);
        g_Wih[mat][kt][ntg][lane] = w2;
    }
    if (idx < 2 * NKT_H * 128 * 32) {           // Whh pack (k = hidden unit 0..255)
        int kt  = q % NKT_H;
        int mat = q / NKT_H;
        const float* Whh = mat ? rWhh : cWhh;
        int k0 = kt * 32 + 4 * tg;
        float v[8];
        #pragma unroll
        for (int i = 0; i < 8; i++) {
            int k = k0 + (i >> 2) * 16 + (i & 3);
            v[i] = SCL * Whh[jo * HID + k];
        }
        uint2 w2;
        w2.x = pack4_e4m3(v[0], v[1], v[2], v[3]);
        w2.y = pack4_e4m3(v[4], v[5], v[6], v[7]);
        g_Whh[mat][kt][ntg][lane] = w2;
    }
}

__global__ void dummy_kernel() {}

// ---------------- xproj: [VOCAB,300] @ [300,1024] + bias -> bf16 table ----------------
__global__ void __launch_bounds__(NTHREADS, 1)
xproj_kernel(const float* emb) {
    __shared__ uint8_t As[MCH * XSB];
    int bid = blockIdx.x;                 // 2 * 1563
    int mat = bid >= 1563;
    int vbase = (bid - mat * 1563) * MCH;

    int tid = threadIdx.x;
    int w = tid >> 5, lane = tid & 31;
    int tg = lane & 3, gg = lane >> 2;

    // zero A (covers k-pad)
    for (int i = tid; i < MCH * XSB / 4; i += NTHREADS)
        ((uint32_t*)As)[i] = 0u;
    __syncthreads();

    // gather embeddings -> fp8 (x16)
    {
        int m = tid >> 4, ts = tid & 15;
        int row = vbase + m; if (row >= VOCAB) row = 0;
        const float4* erow = (const float4*)(emb + (size_t)row * EMBD);
        uint32_t* arow = (uint32_t*)(As + m * XSB);
        for (int kk = ts; kk < EMBD / 4; kk += 16) {
            float4 v = __ldg(&erow[kk]);
            arow[kk] = pack4_e4m3(SCL * v.x, SCL * v.y, SCL * v.z, SCL * v.w);
        }
    }
    __syncthreads();

    float acc[2][8][4];
    #pragma unroll
    for (int mt = 0; mt < 2; mt++)
        #pragma unroll
        for (int nt = 0; nt < 8; nt++)
            #pragma unroll
            for (int i = 0; i < 4; i++) acc[mt][nt][i] = 0.f;

    const uint32_t* Aw = (const uint32_t*)As;
    const uint2* Bp = &g_Wih[mat][0][0][0] + w * 8 * 32 + lane;
    const int a_base = gg * XKW + tg;

    uint2 bb[8];
    #pragma unroll
    for (int nt = 0; nt < 8; nt++) bb[nt] = __ldg(Bp + nt * 32);
    #pragma unroll 2
    for (int kt = 0; kt < NKT_X; kt++) {
        uint2 bn[8];
        if (kt < NKT_X - 1) {
            const uint2* bk2 = Bp + (size_t)(kt + 1) * 128 * 32;
            #pragma unroll
            for (int nt = 0; nt < 8; nt++) bn[nt] = __ldg(bk2 + nt * 32);
        }
        uint32_t a[2][4];
        int ab = a_base + kt * 8;
        #pragma unroll
        for (int mt = 0; mt < 2; mt++) {
            int o = ab + mt * 16 * XKW;
            a[mt][0] = Aw[o];
            a[mt][1] = Aw[o + 8 * XKW];
            a[mt][2] = Aw[o + 4];
            a[mt][3] = Aw[o + 8 * XKW + 4];
        }
        #pragma unroll
        for (int nt = 0; nt < 8; nt++) {
            mma16832(acc[0][nt], a[0], bb[nt]);
            mma16832(acc[1][nt], a[1], bb[nt]);
        }
        #pragma unroll
        for (int nt = 0; nt < 8; nt++) bb[nt] = bn[nt];
    }

    // epilogue: + bias, store bf16 pairs (permuted col order)
    #pragma unroll
    for (int mt = 0; mt < 2; mt++) {
        #pragma unroll
        for (int nt = 0; nt < 8; nt++) {
            int jc = (w << 6) + (nt << 3) + (tg << 1);
            float b0 = g_bias[mat][jc], b1 = g_bias[mat][jc + 1];
            float x0 = acc[mt][nt][0] * ISCL + b0;
            float x1 = acc[mt][nt][1] * ISCL + b1;
            float x2 = acc[mt][nt][2] * ISCL + b0;
            float x3 = acc[mt][nt][3] * ISCL + b1;
            int r0 = vbase + (mt << 4) + gg;
            int r1 = r0 + 8;
            if (r0 < VOCAB)
                *(uint32_t*)&g_xproj[mat][r0][jc] = pack_bf16x2(x0, x1);
            if (r1 < VOCAB)
                *(uint32_t*)&g_xproj[mat][r1][jc] = pack_bf16x2(x2, x3);
        }
    }
}

// ---------------- main recurrent LSTM kernel (k=256) ----------------
__global__ void __launch_bounds__(NTHREADS, 1)
lstm_kernel(const int* colT, const int* rowT, const int* negT,
            const int* clen, const int* rlen, const int* nlen,
            const int* cref, const int* rref, const int* nref) {
    extern __shared__ char smem[];
    uint8_t*   As   = (uint8_t*)(smem + SM_AS);     // [32][272] fp8 h
    float*     Cs   = (float*)(smem + SM_CS);       // [32][257]
    float*     Hs   = (float*)(smem + SM_HS);       // [32][257]
    uint32_t*  xsW  = (uint32_t*)(smem + SM_XS);    // [32][516 words] bf16 xproj+bias
    int*       lensS= (int*)(smem + SM_LENS);
    int*       toksS= (int*)(smem + SM_TOKS);

    int bid = blockIdx.x;
    int task, chunk;
    if (bid < 128) { task = 0; chunk = bid; }
    else           { int j = bid - 128; task = 1 + (j & 1); chunk = j >> 1; }
    int n0 = chunk * MCH;

    const int* toks; const int* lens; const int* refs; int T; int mat;
    if (task == 0)      { toks = colT; lens = clen; refs = cref; T = T_COL; mat = 0; }
    else if (task == 1) { toks = rowT; lens = rlen; refs = rref; T = T_ROW; mat = 1; }
    else                { toks = negT; lens = nlen; refs = nref; T = T_ROW; mat = 1; }

    int tid = threadIdx.x;
    int w = tid >> 5, lane = tid & 31;
    int tg = lane & 3, gg = lane >> 2;

    // --- init smem: h=0, c=0 ---
    for (int i = tid; i < MCH * AKW; i += NTHREADS) ((uint32_t*)As)[i] = 0u;
    for (int i = tid; i < 2 * MCH * 257; i += NTHREADS) Cs[i] = 0.f;
    if (tid < MCH) lensS[tid] = lens[n0 + tid];
    if (tid < MCH) toksS[tid] = toks[(n0 + tid) * T];
    __syncthreads();

    int maxlen = 0;
    #pragma unroll
    for (int i = 0; i < MCH; i++) maxlen = max(maxlen, lensS[i]);

    const uint32_t* Aw = (const uint32_t*)As;
    const uint2* Bp = &g_Whh[mat][0][0][0] + w * 8 * 32 + lane;
    const int a_base = gg * AKW + tg;

    const char* xprow = (const char*)&g_xproj[mat][0][0];
    uint32_t xs_u32;
    { uint64_t t64; asm("{ .reg .u64 a; cvta.to.shared.u64 a, %1; mov.u64 %0, a; }"
                        : "=l"(t64) : "l"((void*)xsW)); xs_u32 = (uint32_t)t64; }

    int gm = tid >> 4, gts = tid & 15;

    for (int t = 0; t < maxlen; t++) {
        // issue xproj gather for this step (overlapped with mma)
        {
            const char* src = xprow + (size_t)toksS[gm] * (GATES * 2) + gts * 16;
            uint32_t dst = xs_u32 + gm * (XS_W * 4) + gts * 16;
            #pragma unroll
            for (int i = 0; i < 8; i++)
                cp_async16(dst + i * 256, src + i * 256);
            asm volatile("cp.async.commit_group;");
        }

        // --- recurrent GEMM: [32,256] @ [256,1024] fp8 ---
        float acc[2][8][4];
        #pragma unroll
        for (int mt = 0; mt < 2; mt++)
            #pragma unroll
            for (int nt = 0; nt < 8; nt++)
                #pragma unroll
                for (int i = 0; i < 4; i++) acc[mt][nt][i] = 0.f;

        uint2 bb[8];
        #pragma unroll
        for (int nt = 0; nt < 8; nt++) bb[nt] = __ldg(Bp + nt * 32);
        #pragma unroll
        for (int kt = 0; kt < NKT_H; kt++) {
            uint2 bn[8];
            if (kt < NKT_H - 1) {
                const uint2* bk2 = Bp + (size_t)(kt + 1) * 128 * 32;
                #pragma unroll
                for (int nt = 0; nt < 8; nt++) bn[nt] = __ldg(bk2 + nt * 32);
            }
            uint32_t a[2][4];
            int ab = a_base + kt * 8;
            #pragma unroll
            for (int mt = 0; mt < 2; mt++) {
                int o = ab + mt * 16 * AKW;
                a[mt][0] = Aw[o];
                a[mt][1] = Aw[o + 8 * AKW];
                a[mt][2] = Aw[o + 4];
                a[mt][3] = Aw[o + 8 * AKW + 4];
            }
            #pragma unroll
            for (int nt = 0; nt < 8; nt++) {
                mma16832(acc[0][nt], a[0], bb[nt]);
                mma16832(acc[1][nt], a[1], bb[nt]);
            }
            #pragma unroll
            for (int nt = 0; nt < 8; nt++) bb[nt] = bn[nt];
        }

        // prefetch next step's tokens
        int tokn = 0;
        if (tid < MCH) {
            int tn = t + 1 < T ? t + 1 : T - 1;
            tokn = toks[(n0 + tid) * T + tn];
        }

        asm volatile("cp.async.wait_group 0;" ::: "memory");
        __syncthreads();   // xs ready; all mma reads of As done

        // --- epilogue: gates = xs + ISCL*acc; cell update ---
        bool ev = !(tg & 1);
        #pragma unroll
        for (int mt = 0; mt < 2; mt++) {
            #pragma unroll
            for (int nt = 0; nt < 8; nt++) {
                int jw = (w << 5) + (nt << 2) + tg;     // (jc>>1)
                int r0 = (mt << 4) + gg;
                float2 gx0 = __bfloat1622float2(
                    *(__nv_bfloat162*)&xsW[r0 * XS_W + jw]);
                float2 gx1 = __bfloat1622float2(
                    *(__nv_bfloat162*)&xsW[(r0 + 8) * XS_W + jw]);
                float x0 = acc[mt][nt][0] * ISCL + gx0.x;
                float x1 = acc[mt][nt][1] * ISCL + gx0.y;
                float x2 = acc[mt][nt][2] * ISCL + gx1.x;
                float x3 = acc[mt][nt][3] * ISCL + gx1.y;
                float y0 = __shfl_xor_sync(0xffffffffu, x0, 1);
                float y1 = __shfl_xor_sync(0xffffffffu, x1, 1);
                float y2 = __shfl_xor_sync(0xffffffffu, x2, 1);
                float y3 = __shfl_xor_sync(0xffffffffu, x3, 1);
                float pi = ev ? x0 : y2;
                float pf = ev ? x1 : y3;
                float pg = ev ? y0 : x2;
                float po = ev ? y1 : x3;
                int mrow = (mt << 4) + gg + (ev ? 0 : 8);
                int u = (w << 4) + (nt << 1) + (tg >> 1);
                if (t < lensS[mrow]) {
                    float i_ = fsigm(pi), f_ = fsigm(pf), o_ = fsigm(po), g_ = ftanh(pg);
                    float cn = f_ * Cs[mrow * 257 + u] + i_ * g_;
                    Cs[mrow * 257 + u] = cn;
                    float hn = o_ * ftanh(cn);
                    Hs[mrow * 257 + u] = hn;
                    As[mrow * ASB + u] = f_to_e4m3(SCL * hn);
                }
            }
        }
        if (tid < MCH) toksS[tid] = tokn;
        __syncthreads();   // h + toks visible for next step
    }

    // --- scatter final h into doc accumulators ---
    if (tid < MCH) toksS[tid] = refs[n0 + tid];
    __syncthreads();
    float* accb = &g_acc[task][0][0];
    for (int idx = tid; idx < MCH * HID; idx += NTHREADS) {
        int m = idx >> 8, u = idx & 255;
        atomicAdd(&accb[toksS[m] * HID + u], Hs[m * 257 + u]);
    }
}

// ---------------- loss ----------------
__global__ void loss_kernel(float* out) {
    int d = blockIdx.x;
    float cv = g_acc[0][d][threadIdx.x], rv = g_acc[1][d][threadIdx.x], nv = g_acc[2][d][threadIdx.x];
    float p = cv * rv, q = cv * nv;
    #pragma unroll
    for (int o = 16; o; o >>= 1) {
        p += __shfl_xor_sync(0xffffffffu, p, o);
        q += __shfl_xor_sync(0xffffffffu, q, o);
    }
    __shared__ float sp[8], sq[8];
    int w = threadIdx.x >> 5, l = threadIdx.x & 31;
    if (l == 0) { sp[w] = p; sq[w] = q; }
    __syncthreads();
    if (threadIdx.x == 0) {
        float P = 0.f, Q = 0.f;
        #pragma unroll
        for (int i = 0; i < 8; i++) { P += sp[i]; Q += sq[i]; }
        float x = P - Q;
        float lz = fmaxf(-x, 0.f) + log1pf(expf(-fabsf(x)));
        if (d == 0) lz += (float)((N_SEQ - N_DOCS) * 0.6931471805599453);
        atomicAdd(out, lz);
    }
}

// ---------------- launch ----------------
extern "C" void kernel_launch(void* const* d_in, const int* in_sizes, int n_in,
                              void* d_out, int out_size) {
    const int*   col   = (const int*)d_in[0];
    const int*   row   = (const int*)d_in[1];
    const int*   rng   = (const int*)d_in[2];
    const int*   clen  = (const int*)d_in[3];
    const int*   rlen  = (const int*)d_in[4];
    const int*   nlen  = (const int*)d_in[5];
    const int*   cref  = (const int*)d_in[6];
    const int*   rref  = (const int*)d_in[7];
    const int*   nref  = (const int*)d_in[8];
    const float* emb   = (const float*)d_in[9];
    const float* cWih  = (const float*)d_in[10];
    const float* cWhh  = (const float*)d_in[11];
    const float* cbih  = (const float*)d_in[12];
    const float* cbhh  = (const float*)d_in[13];
    const float* rWih  = (const float*)d_in[14];
    const float* rWhh  = (const float*)d_in[15];
    const float* rbih  = (const float*)d_in[16];
    const float* rbhh  = (const float*)d_in[17];
    float* out = (float*)d_out;

    cudaFuncSetAttribute(lstm_kernel, cudaFuncAttributeMaxDynamicSharedMemorySize, SMEM_BYTES);

    prep_kernel<<<1536, 256>>>(cWih, cWhh, cbih, cbhh, rWih, rWhh, rbih, rbhh, out);
    xproj_kernel<<<2 * 1563, NTHREADS>>>(emb);
    dummy_kernel<<<1, 32>>>();
    lstm_kernel<<<384, NTHREADS, SMEM_BYTES>>>(col, row, rng, clen, rlen, nlen,
                                               cref, rref, nref);
    loss_kernel<<<N_DOCS, 256>>>(out);
}

// round 6
// speedup vs baseline: 1.3175x; 1.0700x over previous
#include <cuda_runtime.h>
#include <cuda_bf16.h>
#include <cuda_fp8.h>
#include <math.h>
#include <stdint.h>

// Problem constants
#define VOCAB   50000
#define N_SEQ   4096
#define N_DOCS  512
#define EMBD    300
#define HID     256
#define GATES   1024
#define T_COL   64
#define T_ROW   16

#define MCH     16          // sequences per block
#define NT      256         // 8 warps

// recurrence A (h, fp8): k=256 -> 8 kt, row stride 272 B (68 words)
#define NKT_H   8
#define AKW     68
#define ASB     272
// xproj A (emb, fp8): k=300 pad 320 -> 10 kt, row stride 336 B (84 words)
#define NKT_X   10
#define XKW     84
#define XSB     336

#define SCL     16.0f
#define ISCL    0.00390625f // 1/256

// ---------------- device scratch ----------------
__device__ uint2  g_Whh[2][NKT_H][128][32];    // fp8 B fragments (recurrence)
__device__ uint2  g_Wih[2][NKT_X][128][32];    // fp8 B fragments (x-proj)
__device__ float  g_bias[2][GATES];
__device__ __nv_bfloat16 g_xproj[2][VOCAB][GATES];  // 204.8 MB (xproj+bias, permuted cols)
__device__ float  g_acc[3][N_DOCS][HID];

// ---------------- helpers ----------------
__device__ __forceinline__ float ftanh(float x) {
    float y; asm("tanh.approx.f32 %0, %1;" : "=f"(y) : "f"(x)); return y;
}
__device__ __forceinline__ float fsigm(float x) {
    return 0.5f * ftanh(0.5f * x) + 0.5f;
}
__device__ __forceinline__ uint32_t pack4_e4m3(float v0, float v1, float v2, float v3) {
    uint16_t lo, hi;
    asm("cvt.rn.satfinite.e4m3x2.f32 %0, %1, %2;" : "=h"(lo) : "f"(v1), "f"(v0));
    asm("cvt.rn.satfinite.e4m3x2.f32 %0, %1, %2;" : "=h"(hi) : "f"(v3), "f"(v2));
    return (uint32_t)lo | ((uint32_t)hi << 16);
}
__device__ __forceinline__ uint8_t f_to_e4m3(float v) {
    uint16_t r;
    asm("cvt.rn.satfinite.e4m3x2.f32 %0, %1, %2;" : "=h"(r) : "f"(0.f), "f"(v));
    return (uint8_t)r;
}
__device__ __forceinline__ uint32_t pack_bf16x2(float lo, float hi) {
    uint32_t r;
    asm("cvt.rn.bf16x2.f32 %0, %1, %2;" : "=r"(r) : "f"(hi), "f"(lo));
    return r;
}
__device__ __forceinline__ void mma16832(float* c, const uint32_t* a, uint2 b) {
    asm volatile(
        "mma.sync.aligned.m16n8k32.row.col.f32.e4m3.e4m3.f32 "
        "{%0,%1,%2,%3},{%4,%5,%6,%7},{%8,%9},{%0,%1,%2,%3};"
        : "+f"(c[0]), "+f"(c[1]), "+f"(c[2]), "+f"(c[3])
        : "r"(a[0]), "r"(a[1]), "r"(a[2]), "r"(a[3]), "r"(b.x), "r"(b.y));
}

// ---------------- prep: pack weights + bias, zero accumulators ----------------
__global__ void prep_kernel(const float* cWih, const float* cWhh,
                            const float* cbih, const float* cbhh,
                            const float* rWih, const float* rWhh,
                            const float* rbih, const float* rbhh,
                            float* out) {
    int idx = blockIdx.x * blockDim.x + threadIdx.x;   // 393216 threads
    if (idx == 0) *out = 0.f;
    if (idx < 3 * N_DOCS * HID) (&g_acc[0][0][0])[idx] = 0.f;

    if (idx < 2 * GATES) {
        int bm = idx >> 10, jb = idx & 1023;
        int jbo = (jb & 3) * 256 + (jb >> 2);
        const float* bih = bm ? rbih : cbih;
        const float* bhh = bm ? rbhh : cbhh;
        g_bias[bm][jb] = bih[jbo] + bhh[jbo];
    }

    int lane = idx & 31;
    int ntg  = (idx >> 5) & 127;
    int q    = idx >> 12;
    int tg = lane & 3, gg = lane >> 2;
    int jp = ntg * 8 + gg;
    int jo = (jp & 3) * 256 + (jp >> 2);

    if (idx < 2 * NKT_X * 128 * 32) {           // Wih pack (k 0..299 pad 320)
        int kt  = q % NKT_X;
        int mat = q / NKT_X;
        const float* Wih = mat ? rWih : cWih;
        int k0 = kt * 32 + 4 * tg;
        float v[8];
        #pragma unroll
        for (int i = 0; i < 8; i++) {
            int k = k0 + (i >> 2) * 16 + (i & 3);
            v[i] = (k < EMBD) ? SCL * Wih[jo * EMBD + k] : 0.f;
        }
        uint2 w2;
        w2.x = pack4_e4m3(v[0], v[1], v[2], v[3]);
        w2.y = pack4_e4m3(v[4], v[5], v[6], v[7]);
        g_Wih[mat][kt][ntg][lane] = w2;
    }
    if (idx < 2 * NKT_H * 128 * 32) {           // Whh pack (k = hidden unit)
        int kt  = q % NKT_H;
        int mat = q / NKT_H;
        const float* Whh = mat ? rWhh : cWhh;
        int k0 = kt * 32 + 4 * tg;
        float v[8];
        #pragma unroll
        for (int i = 0; i < 8; i++) {
            int k = k0 + (i >> 2) * 16 + (i & 3);
            v[i] = SCL * Whh[jo * HID + k];
        }
        uint2 w2;
        w2.x = pack4_e4m3(v[0], v[1], v[2], v[3]);
        w2.y = pack4_e4m3(v[4], v[5], v[6], v[7]);
        g_Whh[mat][kt][ntg][lane] = w2;
    }
}

// ---------------- xproj: [VOCAB,300]@[300,1024] + bias -> bf16 table ----------------
__global__ void __launch_bounds__(NT, 2)
xproj_kernel(const float* emb) {
    __shared__ uint8_t As[32 * XSB];       // 10752 B
    int bid = blockIdx.x;                  // 2 * 1563
    int mat = bid >= 1563;
    int vbase = (bid - mat * 1563) * 32;

    int tid = threadIdx.x;
    int w = tid >> 5, lane = tid & 31;
    int tg = lane & 3, gg = lane >> 2;

    for (int i = tid; i < 32 * XSB / 4; i += NT) ((uint32_t*)As)[i] = 0u;
    __syncthreads();

    {   // gather embeddings -> fp8 (x16): 8 threads per row
        int m = tid >> 3, ts = tid & 7;
        int row = vbase + m; if (row >= VOCAB) row = 0;
        const float4* erow = (const float4*)(emb + (size_t)row * EMBD);
        uint32_t* arow = (uint32_t*)(As + m * XSB);
        for (int kk = ts; kk < EMBD / 4; kk += 8) {
            float4 v = __ldg(&erow[kk]);
            arow[kk] = pack4_e4m3(SCL * v.x, SCL * v.y, SCL * v.z, SCL * v.w);
        }
    }
    __syncthreads();

    const uint32_t* Aw = (const uint32_t*)As;
    const int a_base = gg * XKW + tg;

    #pragma unroll
    for (int h = 0; h < 2; h++) {
        int nt_base = (w << 4) + (h << 3);
        const uint2* Bp = &g_Wih[mat][0][0][0] + nt_base * 32 + lane;

        float acc[2][8][4];
        #pragma unroll
        for (int mt = 0; mt < 2; mt++)
            #pragma unroll
            for (int nt = 0; nt < 8; nt++)
                #pragma unroll
                for (int i = 0; i < 4; i++) acc[mt][nt][i] = 0.f;

        uint2 bb[8];
        #pragma unroll
        for (int nt = 0; nt < 8; nt++) bb[nt] = __ldg(Bp + nt * 32);
        #pragma unroll
        for (int kt = 0; kt < NKT_X; kt++) {
            uint2 bn[8];
            if (kt < NKT_X - 1) {
                const uint2* bk2 = Bp + (size_t)(kt + 1) * 128 * 32;
                #pragma unroll
                for (int nt = 0; nt < 8; nt++) bn[nt] = __ldg(bk2 + nt * 32);
            }
            uint32_t a[2][4];
            int ab = a_base + kt * 8;
            #pragma unroll
            for (int mt = 0; mt < 2; mt++) {
                int o = ab + mt * 16 * XKW;
                a[mt][0] = Aw[o];
                a[mt][1] = Aw[o + 8 * XKW];
                a[mt][2] = Aw[o + 4];
                a[mt][3] = Aw[o + 8 * XKW + 4];
            }
            #pragma unroll
            for (int nt = 0; nt < 8; nt++) {
                mma16832(acc[0][nt], a[0], bb[nt]);
                mma16832(acc[1][nt], a[1], bb[nt]);
            }
            #pragma unroll
            for (int nt = 0; nt < 8; nt++) bb[nt] = bn[nt];
        }

        // epilogue: +bias, store bf16x2 at permuted cols
        #pragma unroll
        for (int nt = 0; nt < 8; nt++) {
            int jc = ((nt_base + nt) << 3) + (tg << 1);
            float b0 = g_bias[mat][jc], b1 = g_bias[mat][jc + 1];
            #pragma unroll
            for (int mt = 0; mt < 2; mt++) {
                int r0 = vbase + (mt << 4) + gg;
                int r1 = r0 + 8;
                if (r0 < VOCAB)
                    *(uint32_t*)&g_xproj[mat][r0][jc] =
                        pack_bf16x2(acc[mt][nt][0] * ISCL + b0, acc[mt][nt][1] * ISCL + b1);
                if (r1 < VOCAB)
                    *(uint32_t*)&g_xproj[mat][r1][jc] =
                        pack_bf16x2(acc[mt][nt][2] * ISCL + b0, acc[mt][nt][3] * ISCL + b1);
            }
        }
    }
}

// ---------------- main recurrent LSTM kernel (M=16, k=256) ----------------
__global__ void __launch_bounds__(NT, 2)
lstm_kernel(const int* colT, const int* rowT, const int* negT,
            const int* clen, const int* rlen, const int* nlen,
            const int* cref, const int* rref, const int* nref) {
    __shared__ uint8_t        As0[MCH * ASB];        // 4352
    __shared__ uint8_t        As1[MCH * ASB];        // 4352
    __shared__ float          Cs[MCH * 257];         // 16448
    __shared__ __nv_bfloat16  Hs[MCH * 264];         // 8448
    __shared__ int            toksAll[MCH * T_COL];  // 4096
    __shared__ int            lensS[MCH];
    __shared__ int            refS[MCH];

    int bid = blockIdx.x;
    int task, chunk;
    if (bid < 256) { task = 0; chunk = bid; }
    else           { int j = bid - 256; task = 1 + (j & 1); chunk = j >> 1; }
    int n0 = chunk * MCH;

    const int* toks; const int* lens; const int* refs; int T; int mat;
    if (task == 0)      { toks = colT; lens = clen; refs = cref; T = T_COL; mat = 0; }
    else if (task == 1) { toks = rowT; lens = rlen; refs = rref; T = T_ROW; mat = 1; }
    else                { toks = negT; lens = nlen; refs = nref; T = T_ROW; mat = 1; }

    int tid = threadIdx.x;
    int w = tid >> 5, lane = tid & 31;
    int tg = lane & 3, gg = lane >> 2;

    // init: zero As0 + Cs; load all tokens + lens
    for (int i = tid; i < MCH * ASB / 4; i += NT) ((uint32_t*)As0)[i] = 0u;
    for (int i = tid; i < MCH * 257; i += NT) Cs[i] = 0.f;
    for (int i = tid; i < MCH * T; i += NT) toksAll[i] = toks[n0 * T + i];
    if (tid < MCH) lensS[tid] = lens[n0 + tid];
    __syncthreads();

    int maxlen = lensS[0];    // lengths sorted descending

    const int a_base = gg * AKW + tg;
    const uint2* Bmat = &g_Whh[mat][0][0][0];
    const __nv_bfloat16* xpb = &g_xproj[mat][0][0];
    bool ev = !(tg & 1);
    int len0 = lensS[gg], len1 = lensS[gg + 8];
    int lenm = ev ? len0 : len1;
    int mrow = ev ? gg : gg + 8;

    for (int t = 0; t < maxlen; t++) {
        const uint32_t* ArW = (const uint32_t*)((t & 1) ? As1 : As0);
        uint8_t*        AwB = (t & 1) ? As0 : As1;
        const uint8_t*  ArB = (const uint8_t*)ArW;

        int tok0 = toksAll[gg * T + t];
        int tok1 = toksAll[(gg + 8) * T + t];
        const uint32_t* xp0 = (const uint32_t*)(xpb + (size_t)tok0 * GATES);
        const uint32_t* xp1 = (const uint32_t*)(xpb + (size_t)tok1 * GATES);

        #pragma unroll
        for (int h = 0; h < 2; h++) {
            int nt_base = (w << 4) + (h << 3);
            const uint2* Bp = Bmat + nt_base * 32 + lane;

            // batched gx loads for this half (overlap with mma below)
            uint32_t gx0[8], gx1[8];
            #pragma unroll
            for (int nt = 0; nt < 8; nt++) {
                int jw = ((nt_base + nt) << 2) + tg;
                gx0[nt] = __ldg(xp0 + jw);
                gx1[nt] = __ldg(xp1 + jw);
            }

            float acc[8][4];
            #pragma unroll
            for (int nt = 0; nt < 8; nt++)
                #pragma unroll
                for (int i = 0; i < 4; i++) acc[nt][i] = 0.f;

            uint2 bb[8];
            #pragma unroll
            for (int nt = 0; nt < 8; nt++) bb[nt] = __ldg(Bp + nt * 32);
            #pragma unroll
            for (int kt = 0; kt < NKT_H; kt++) {
                uint2 bn[8];
                if (kt < NKT_H - 1) {
                    const uint2* bk2 = Bp + (size_t)(kt + 1) * 128 * 32;
                    #pragma unroll
                    for (int nt = 0; nt < 8; nt++) bn[nt] = __ldg(bk2 + nt * 32);
                }
                int o = a_base + kt * 8;
                uint32_t a[4];
                a[0] = ArW[o];
                a[1] = ArW[o + 8 * AKW];
                a[2] = ArW[o + 4];
                a[3] = ArW[o + 8 * AKW + 4];
                #pragma unroll
                for (int nt = 0; nt < 8; nt++) mma16832(acc[nt], a, bb[nt]);
                #pragma unroll
                for (int nt = 0; nt < 8; nt++) bb[nt] = bn[nt];
            }

            // epilogue for this half
            #pragma unroll
            for (int nt = 0; nt < 8; nt++) {
                __nv_bfloat162 h0 = *(__nv_bfloat162*)&gx0[nt];
                __nv_bfloat162 h1 = *(__nv_bfloat162*)&gx1[nt];
                float2 g0 = __bfloat1622float2(h0);
                float2 g1 = __bfloat1622float2(h1);
                float x0 = acc[nt][0] * ISCL + g0.x;
                float x1 = acc[nt][1] * ISCL + g0.y;
                float x2 = acc[nt][2] * ISCL + g1.x;
                float x3 = acc[nt][3] * ISCL + g1.y;
                float y0 = __shfl_xor_sync(0xffffffffu, x0, 1);
                float y1 = __shfl_xor_sync(0xffffffffu, x1, 1);
                float y2 = __shfl_xor_sync(0xffffffffu, x2, 1);
                float y3 = __shfl_xor_sync(0xffffffffu, x3, 1);
                float pi = ev ? x0 : y2;
                float pf = ev ? x1 : y3;
                float pg = ev ? y0 : x2;
                float po = ev ? y1 : x3;
                int u = ((nt_base + nt) << 1) + (tg >> 1);
                int ai = mrow * ASB + u;
                if (t < lenm) {
                    float i_ = fsigm(pi), f_ = fsigm(pf), o_ = fsigm(po), g_ = ftanh(pg);
                    int ci = mrow * 257 + u;
                    float cn = f_ * Cs[ci] + i_ * g_;
                    Cs[ci] = cn;
                    float hn = o_ * ftanh(cn);
                    Hs[mrow * 264 + u] = __float2bfloat16(hn);
                    AwB[ai] = f_to_e4m3(SCL * hn);
                } else {
                    AwB[ai] = ArB[ai];   // carry frozen h forward
                }
            }
        }
        __syncthreads();   // new As buffer visible to all warps
    }

    // scatter final h into doc accumulators
    if (tid < MCH) refS[tid] = refs[n0 + tid];
    __syncthreads();
    float* accb = &g_acc[task][0][0];
    for (int idx = tid; idx < MCH * HID; idx += NT) {
        int m = idx >> 8, u = idx & 255;
        atomicAdd(&accb[refS[m] * HID + u], __bfloat162float(Hs[m * 264 + u]));
    }
}

// ---------------- loss ----------------
__global__ void loss_kernel(float* out) {
    int d = blockIdx.x;
    float cv = g_acc[0][d][threadIdx.x], rv = g_acc[1][d][threadIdx.x], nv = g_acc[2][d][threadIdx.x];
    float p = cv * rv, q = cv * nv;
    #pragma unroll
    for (int o = 16; o; o >>= 1) {
        p += __shfl_xor_sync(0xffffffffu, p, o);
        q += __shfl_xor_sync(0xffffffffu, q, o);
    }
    __shared__ float sp[8], sq[8];
    int w = threadIdx.x >> 5, l = threadIdx.x & 31;
    if (l == 0) { sp[w] = p; sq[w] = q; }
    __syncthreads();
    if (threadIdx.x == 0) {
        float P = 0.f, Q = 0.f;
        #pragma unroll
        for (int i = 0; i < 8; i++) { P += sp[i]; Q += sq[i]; }
        float x = P - Q;
        float lz = fmaxf(-x, 0.f) + log1pf(expf(-fabsf(x)));
        if (d == 0) lz += (float)((N_SEQ - N_DOCS) * 0.6931471805599453);
        atomicAdd(out, lz);
    }
}

// ---------------- launch ----------------
extern "C" void kernel_launch(void* const* d_in, const int* in_sizes, int n_in,
                              void* d_out, int out_size) {
    const int*   col   = (const int*)d_in[0];
    const int*   row   = (const int*)d_in[1];
    const int*   rng   = (const int*)d_in[2];
    const int*   clen  = (const int*)d_in[3];
    const int*   rlen  = (const int*)d_in[4];
    const int*   nlen  = (const int*)d_in[5];
    const int*   cref  = (const int*)d_in[6];
    const int*   rref  = (const int*)d_in[7];
    const int*   nref  = (const int*)d_in[8];
    const float* emb   = (const float*)d_in[9];
    const float* cWih  = (const float*)d_in[10];
    const float* cWhh  = (const float*)d_in[11];
    const float* cbih  = (const float*)d_in[12];
    const float* cbhh  = (const float*)d_in[13];
    const float* rWih  = (const float*)d_in[14];
    const float* rWhh  = (const float*)d_in[15];
    const float* rbih  = (const float*)d_in[16];
    const float* rbhh  = (const float*)d_in[17];
    float* out = (float*)d_out;

    prep_kernel<<<1536, 256>>>(cWih, cWhh, cbih, cbhh, rWih, rWhh, rbih, rbhh, out);
    xproj_kernel<<<2 * 1563, NT>>>(emb);
    lstm_kernel<<<768, NT>>>(col, row, rng, clen, rlen, nlen, cref, rref, nref);
    loss_kernel<<<N_DOCS, 256>>>(out);
}